// round 2
// baseline (speedup 1.0000x reference)
#include <cuda_runtime.h>
#include <cuda_bf16.h>
#include <math.h>

// ---------------- problem constants ----------------
#define B_   64
#define T_   512
#define D_   256
#define FF_  512
#define L_   4
#define H_   8
#define HD_  32
#define M_   (B_*T_)          // 32768 rows

// ---------------- scratch (device globals; no allocation allowed) ----------------
__device__ float g_x   [M_*D_];     // running residual stream
__device__ float g_ln  [M_*D_];     // layernorm output
__device__ float g_qkv [M_*3*D_];   // qkv projections
__device__ float g_attn[M_*D_];     // attention output
__device__ float g_h1  [M_*FF_];    // ffn hidden
__device__ int   g_mask_u8;         // 1 if mask buffer is u8/bool, 0 if int32

// ---------------- mask dtype detection ----------------
// If mask is int32 (values 0/1), every byte at offset %4 != 0 is zero.
// If mask is u8/bool, ~3/8 of those bytes are nonzero. Deterministic.
__global__ void detect_mask_kernel(const unsigned char* __restrict__ m)
{
    __shared__ int s_any;
    if (threadIdx.x == 0) s_any = 0;
    __syncthreads();
    int any = 0;
    for (int i = threadIdx.x; i < M_; i += 256)
        if ((i & 3) && m[i]) any = 1;
    if (any) atomicOr(&s_any, 1);
    __syncthreads();
    if (threadIdx.x == 0) g_mask_u8 = s_any;
}

// ---------------- embedding ----------------
__global__ void embed_kernel(const float* __restrict__ latents,
                             const int*   __restrict__ move_ids,
                             const float* __restrict__ pos,
                             const float* __restrict__ efrom,
                             const float* __restrict__ eto,
                             const float* __restrict__ epromo)
{
    int row = blockIdx.x;            // b*T + t
    int d   = threadIdx.x;           // 0..255
    int t   = row & (T_-1);
    int mid = move_ids[row];
    int promo = mid >> 12;           // /4096
    int rem   = mid & 4095;
    int frm   = rem >> 6;            // /64
    int to    = rem & 63;
    size_t off = (size_t)row * D_ + d;
    g_x[off] = latents[off] + pos[t*D_ + d] + efrom[frm*D_ + d]
             + eto[to*D_ + d] + epromo[promo*D_ + d];
}

// ---------------- block reduce (256 threads) ----------------
__device__ __forceinline__ float blockReduceSum256(float v, float* red)
{
    __syncthreads();                 // protect smem reuse across calls
    #pragma unroll
    for (int off = 16; off; off >>= 1) v += __shfl_xor_sync(0xffffffffu, v, off);
    int w = threadIdx.x >> 5;
    if ((threadIdx.x & 31) == 0) red[w] = v;
    __syncthreads();
    if (w == 0) {
        float s = (threadIdx.x < 8) ? red[threadIdx.x] : 0.f;
        s += __shfl_xor_sync(0xffffffffu, s, 4);
        s += __shfl_xor_sync(0xffffffffu, s, 2);
        s += __shfl_xor_sync(0xffffffffu, s, 1);
        if (threadIdx.x == 0) red[0] = s;
    }
    __syncthreads();
    return red[0];
}

// ---------------- layernorm: one CTA per row ----------------
__global__ void ln_kernel(const float* __restrict__ x,
                          const float* __restrict__ w,
                          const float* __restrict__ b,
                          float* __restrict__ y)
{
    __shared__ float red[8];
    size_t base = (size_t)blockIdx.x * D_;
    int t = threadIdx.x;
    float v = x[base + t];
    float mean = blockReduceSum256(v, red) * (1.f/(float)D_);
    float d = v - mean;
    float var = blockReduceSum256(d*d, red) * (1.f/(float)D_);
    y[base + t] = d * rsqrtf(var + 1e-5f) * w[t] + b[t];
}

// final layernorm + mask-select, writes d_out
__global__ void ln_mask_kernel(const float* __restrict__ x,
                               const float* __restrict__ w,
                               const float* __restrict__ b,
                               const unsigned char* __restrict__ mask_u8,
                               const int*           __restrict__ mask_i32,
                               const float* __restrict__ latents,
                               float* __restrict__ out)
{
    __shared__ float red[8];
    int row = blockIdx.x;
    size_t base = (size_t)row * D_;
    int t = threadIdx.x;
    float v = x[base + t];
    float mean = blockReduceSum256(v, red) * (1.f/(float)D_);
    float d = v - mean;
    float var = blockReduceSum256(d*d, red) * (1.f/(float)D_);
    float val = d * rsqrtf(var + 1e-5f) * w[t] + b[t];
    int m = g_mask_u8 ? (int)mask_u8[row] : mask_i32[row];
    out[base + t] = m ? val : latents[base + t];
}

// ---------------- SGEMM: C[M,N] (+)= A[M,K] @ W[N,K]^T + bias[N] ----------------
// BM=BN=64, BK=32, 256 threads, 4x4 micro-tile per thread.
// Smem stored transposed with stride 65 -> conflict-free STS and LDS.
template<bool RESID, bool RELU>
__global__ void gemm_kernel(const float* __restrict__ A,
                            const float* __restrict__ W,
                            const float* __restrict__ bias,
                            float* __restrict__ C,
                            int M, int N, int K)
{
    const int BM = 64, BN = 64, BK = 32, STR = 65;
    __shared__ float As[BK * STR];
    __shared__ float Bs[BK * STR];
    int tid = threadIdx.x;
    int tx = tid & 15, ty = tid >> 4;
    int bm = blockIdx.y * BM, bn = blockIdx.x * BN;

    float acc[4][4] = {};
    for (int k0 = 0; k0 < K; k0 += BK) {
        #pragma unroll
        for (int r = 0; r < 2; ++r) {
            int e   = tid + r * 256;       // 0..511 float4 slots
            int row = e >> 3;              // 8 float4 per row
            int c4  = (e & 7) * 4;
            float4 a = *(const float4*)(A + (size_t)(bm + row) * K + k0 + c4);
            As[(c4+0)*STR + row] = a.x; As[(c4+1)*STR + row] = a.y;
            As[(c4+2)*STR + row] = a.z; As[(c4+3)*STR + row] = a.w;
            float4 b = *(const float4*)(W + (size_t)(bn + row) * K + k0 + c4);
            Bs[(c4+0)*STR + row] = b.x; Bs[(c4+1)*STR + row] = b.y;
            Bs[(c4+2)*STR + row] = b.z; Bs[(c4+3)*STR + row] = b.w;
        }
        __syncthreads();
        #pragma unroll
        for (int k = 0; k < BK; ++k) {
            float av[4], bv[4];
            #pragma unroll
            for (int i = 0; i < 4; ++i) av[i] = As[k*STR + ty*4 + i];
            #pragma unroll
            for (int j = 0; j < 4; ++j) bv[j] = Bs[k*STR + tx*4 + j];
            #pragma unroll
            for (int i = 0; i < 4; ++i)
                #pragma unroll
                for (int j = 0; j < 4; ++j)
                    acc[i][j] = fmaf(av[i], bv[j], acc[i][j]);
        }
        __syncthreads();
    }
    #pragma unroll
    for (int i = 0; i < 4; ++i) {
        int m = bm + ty*4 + i;
        #pragma unroll
        for (int j = 0; j < 4; ++j) {
            int n = bn + tx*4 + j;
            float v = acc[i][j] + bias[n];
            if (RELU) v = fmaxf(v, 0.f);
            float* p = C + (size_t)m * N + n;
            if (RESID) *p += v; else *p = v;
        }
    }
}

// ---------------- attention: one CTA per (b,h), full K/V in smem ----------------
// stride-33 smem rows: conflict-free for both QK (lane->j) and PV (lane->d) phases.
#define KV_STRIDE 33
#define ATTN_SMEM (2 * T_ * KV_STRIDE * 4)

__global__ void attn_kernel(const float* __restrict__ qkv,
                            float* __restrict__ attn_out)
{
    extern __shared__ float sm[];
    float* Ksh = sm;
    float* Vsh = sm + T_ * KV_STRIDE;

    int bh   = blockIdx.x;
    int b    = bh >> 3;
    int h    = bh & 7;
    int tid  = threadIdx.x;          // 512 threads = 16 warps
    int lane = tid & 31;
    int w    = tid >> 5;

    const float* kvbase = qkv + (size_t)b * T_ * (3*D_) + h * HD_;
    for (int idx = tid; idx < T_ * HD_; idx += 512) {
        int j = idx >> 5, d = idx & 31;
        Ksh[j*KV_STRIDE + d] = kvbase[(size_t)j * (3*D_) + D_   + d];
        Vsh[j*KV_STRIDE + d] = kvbase[(size_t)j * (3*D_) + 2*D_ + d];
    }
    __syncthreads();

    const float scale = 0.17677669529663687f;  // 1/sqrt(32)

    for (int qi = 0; qi < 32; ++qi) {
        int i = qi * 16 + w;                    // balanced query distribution
        // load q (uniform per warp)
        float q[HD_];
        const float4* qp = (const float4*)(qkv + (size_t)(b*T_ + i) * (3*D_) + h * HD_);
        #pragma unroll
        for (int c = 0; c < 8; ++c) {
            float4 f = qp[c];
            q[4*c] = f.x; q[4*c+1] = f.y; q[4*c+2] = f.z; q[4*c+3] = f.w;
        }
        int jmax = ((i >> 3) + 1) << 3;         // block-causal bound
        int nsl  = (jmax + 31) >> 5;

        float s[16];
        float mx = -1e30f;
        #pragma unroll
        for (int slot = 0; slot < 16; ++slot) {
            float val = -1e30f;
            int j = slot * 32 + lane;
            if (slot < nsl && j < jmax) {
                const float* kr = Ksh + j * KV_STRIDE;
                float dot = 0.f;
                #pragma unroll
                for (int d = 0; d < HD_; ++d) dot = fmaf(q[d], kr[d], dot);
                val = dot * scale;
            }
            s[slot] = val;
            mx = fmaxf(mx, val);
        }
        #pragma unroll
        for (int off = 16; off; off >>= 1)
            mx = fmaxf(mx, __shfl_xor_sync(0xffffffffu, mx, off));

        float Z = 0.f;
        #pragma unroll
        for (int slot = 0; slot < 16; ++slot) {
            float p = __expf(s[slot] - mx);     // masked slots: exp(-1e30)=0
            s[slot] = p;
            Z += p;
        }
        #pragma unroll
        for (int off = 16; off; off >>= 1)
            Z += __shfl_xor_sync(0xffffffffu, Z, off);
        float inv = 1.f / Z;

        float acc = 0.f;
        #pragma unroll
        for (int slot = 0; slot < 16; ++slot) {
            int jbase = slot * 32;
            if (jbase >= jmax) break;
            float ps = s[slot];
            int cnt = min(32, jmax - jbase);
            const float* vcol = Vsh + jbase * KV_STRIDE + lane;
            for (int src = 0; src < cnt; ++src) {
                float p = __shfl_sync(0xffffffffu, ps, src);
                acc = fmaf(p, vcol[src * KV_STRIDE], acc);
            }
        }
        attn_out[(size_t)(b*T_ + i) * D_ + h * HD_ + lane] = acc * inv;
    }
}

// ---------------- launch ----------------
extern "C" void kernel_launch(void* const* d_in, const int* in_sizes, int n_in,
                              void* d_out, int out_size)
{
    const float*         latents  = (const float*)d_in[0];
    const int*           move_ids = (const int*)d_in[1];
    const void*          mask     = d_in[2];
    const float*         pos      = (const float*)d_in[3];
    const float*         efrom    = (const float*)d_in[4];
    const float*         eto      = (const float*)d_in[5];
    const float*         epromo   = (const float*)d_in[6];
    const float*         in_proj_w= (const float*)d_in[7];
    const float*         in_proj_b= (const float*)d_in[8];
    const float*         out_w    = (const float*)d_in[9];
    const float*         out_b    = (const float*)d_in[10];
    const float*         fc1_w    = (const float*)d_in[11];
    const float*         fc1_b    = (const float*)d_in[12];
    const float*         fc2_w    = (const float*)d_in[13];
    const float*         fc2_b    = (const float*)d_in[14];
    const float*         norm_w   = (const float*)d_in[15];
    const float*         norm_b   = (const float*)d_in[16];
    float* out = (float*)d_out;

    float *px, *pln, *pqkv, *pattn, *ph1;
    cudaGetSymbolAddress((void**)&px,    g_x);
    cudaGetSymbolAddress((void**)&pln,   g_ln);
    cudaGetSymbolAddress((void**)&pqkv,  g_qkv);
    cudaGetSymbolAddress((void**)&pattn, g_attn);
    cudaGetSymbolAddress((void**)&ph1,   g_h1);

    cudaFuncSetAttribute(attn_kernel,
                         cudaFuncAttributeMaxDynamicSharedMemorySize, ATTN_SMEM);

    detect_mask_kernel<<<1, 256>>>((const unsigned char*)mask);
    embed_kernel<<<M_, 256>>>(latents, move_ids, pos, efrom, eto, epromo);

    for (int l = 0; l < L_; ++l) {
        ln_kernel<<<M_, 256>>>(px, norm_w, norm_b, pln);
        gemm_kernel<false,false><<<dim3(3*D_/64, M_/64), 256>>>(
            pln, in_proj_w + (size_t)l*3*D_*D_, in_proj_b + l*3*D_, pqkv, M_, 3*D_, D_);
        attn_kernel<<<B_*H_, 512, ATTN_SMEM>>>(pqkv, pattn);
        gemm_kernel<true,false><<<dim3(D_/64, M_/64), 256>>>(
            pattn, out_w + (size_t)l*D_*D_, out_b + l*D_, px, M_, D_, D_);
        ln_kernel<<<M_, 256>>>(px, norm_w, norm_b, pln);
        gemm_kernel<false,true><<<dim3(FF_/64, M_/64), 256>>>(
            pln, fc1_w + (size_t)l*FF_*D_, fc1_b + l*FF_, ph1, M_, FF_, D_);
        gemm_kernel<true,false><<<dim3(D_/64, M_/64), 256>>>(
            ph1, fc2_w + (size_t)l*D_*FF_, fc2_b + l*D_, px, M_, D_, FF_);
    }

    ln_mask_kernel<<<M_, 256>>>(px, norm_w, norm_b,
                                (const unsigned char*)mask, (const int*)mask,
                                latents, out);
}

// round 3
// speedup vs baseline: 1.5036x; 1.5036x over previous
#include <cuda_runtime.h>
#include <cuda_bf16.h>
#include <math.h>
#include <stdint.h>

// ---------------- problem constants ----------------
#define B_   64
#define T_   512
#define D_   256
#define FF_  512
#define L_   4
#define H_   8
#define HD_  32
#define M_   (B_*T_)          // 32768 rows

// ---------------- scratch (device globals; no allocation allowed) ----------------
__device__ float g_x   [M_*D_];     // running residual stream
__device__ float g_ln  [M_*D_];     // layernorm output
__device__ float g_qkv [M_*3*D_];   // qkv projections
__device__ float g_attn[M_*D_];     // attention output
__device__ float g_h1  [M_*FF_];    // ffn hidden
__device__ int   g_mask_u8;         // 1 if mask buffer is u8/bool, 0 if int32

// ---------------- mask dtype detection ----------------
__global__ void detect_mask_kernel(const unsigned char* __restrict__ m)
{
    __shared__ int s_any;
    if (threadIdx.x == 0) s_any = 0;
    __syncthreads();
    int any = 0;
    for (int i = threadIdx.x; i < M_; i += 256)
        if ((i & 3) && m[i]) any = 1;
    if (any) atomicOr(&s_any, 1);
    __syncthreads();
    if (threadIdx.x == 0) g_mask_u8 = s_any;
}

// ---------------- embedding ----------------
__global__ void embed_kernel(const float* __restrict__ latents,
                             const int*   __restrict__ move_ids,
                             const float* __restrict__ pos,
                             const float* __restrict__ efrom,
                             const float* __restrict__ eto,
                             const float* __restrict__ epromo)
{
    int row = blockIdx.x;
    int d   = threadIdx.x;
    int t   = row & (T_-1);
    int mid = move_ids[row];
    int promo = mid >> 12;
    int rem   = mid & 4095;
    int frm   = rem >> 6;
    int to    = rem & 63;
    size_t off = (size_t)row * D_ + d;
    g_x[off] = latents[off] + pos[t*D_ + d] + efrom[frm*D_ + d]
             + eto[to*D_ + d] + epromo[promo*D_ + d];
}

// ---------------- block reduce (256 threads) ----------------
__device__ __forceinline__ float blockReduceSum256(float v, float* red)
{
    __syncthreads();
    #pragma unroll
    for (int off = 16; off; off >>= 1) v += __shfl_xor_sync(0xffffffffu, v, off);
    int w = threadIdx.x >> 5;
    if ((threadIdx.x & 31) == 0) red[w] = v;
    __syncthreads();
    if (w == 0) {
        float s = (threadIdx.x < 8) ? red[threadIdx.x] : 0.f;
        s += __shfl_xor_sync(0xffffffffu, s, 4);
        s += __shfl_xor_sync(0xffffffffu, s, 2);
        s += __shfl_xor_sync(0xffffffffu, s, 1);
        if (threadIdx.x == 0) red[0] = s;
    }
    __syncthreads();
    return red[0];
}

// ---------------- layernorm: one CTA per row ----------------
__global__ void ln_kernel(const float* __restrict__ x,
                          const float* __restrict__ w,
                          const float* __restrict__ b,
                          float* __restrict__ y)
{
    __shared__ float red[8];
    size_t base = (size_t)blockIdx.x * D_;
    int t = threadIdx.x;
    float v = x[base + t];
    float mean = blockReduceSum256(v, red) * (1.f/(float)D_);
    float d = v - mean;
    float var = blockReduceSum256(d*d, red) * (1.f/(float)D_);
    y[base + t] = d * rsqrtf(var + 1e-5f) * w[t] + b[t];
}

// final layernorm + mask-select, writes d_out
__global__ void ln_mask_kernel(const float* __restrict__ x,
                               const float* __restrict__ w,
                               const float* __restrict__ b,
                               const unsigned char* __restrict__ mask_u8,
                               const int*           __restrict__ mask_i32,
                               const float* __restrict__ latents,
                               float* __restrict__ out)
{
    __shared__ float red[8];
    int row = blockIdx.x;
    size_t base = (size_t)row * D_;
    int t = threadIdx.x;
    float v = x[base + t];
    float mean = blockReduceSum256(v, red) * (1.f/(float)D_);
    float d = v - mean;
    float var = blockReduceSum256(d*d, red) * (1.f/(float)D_);
    float val = d * rsqrtf(var + 1e-5f) * w[t] + b[t];
    int m = g_mask_u8 ? (int)mask_u8[row] : mask_i32[row];
    out[base + t] = m ? val : latents[base + t];
}

// ---------------- tf32 tensor-core GEMM ----------------
// C[M,N] (+)= A[M,K] @ W[N,K]^T + bias[N]
// BM=128, BN=64, BK=32, 256 threads (8 warps, 4x2), warp tile 32x32,
// mma.sync m16n8k8 tf32. Smem row stride 36 floats -> LDS bank = 4g+tg,
// all 32 lanes distinct (conflict-free fragment loads).
__device__ __forceinline__ float cvt_tf32(float x)
{
    uint32_t u;
    asm("cvt.rna.tf32.f32 %0, %1;" : "=r"(u) : "f"(x));
    return __uint_as_float(u);
}

__device__ __forceinline__ void mma_tf32(float* d, const uint32_t* a, const uint32_t* b)
{
    asm volatile(
        "mma.sync.aligned.m16n8k8.row.col.f32.tf32.tf32.f32 "
        "{%0,%1,%2,%3},{%4,%5,%6,%7},{%8,%9},{%0,%1,%2,%3};"
        : "+f"(d[0]), "+f"(d[1]), "+f"(d[2]), "+f"(d[3])
        : "r"(a[0]), "r"(a[1]), "r"(a[2]), "r"(a[3]), "r"(b[0]), "r"(b[1]));
}

#define GSTR 36

template<bool RESID, bool RELU>
__global__ void gemm_tf32_kernel(const float* __restrict__ A,
                                 const float* __restrict__ W,
                                 const float* __restrict__ bias,
                                 float* __restrict__ C,
                                 int M, int N, int K)
{
    __shared__ float As[128 * GSTR];   // [m][k], 18KB
    __shared__ float Bs[ 64 * GSTR];   // [n][k],  9KB

    int tid  = threadIdx.x;
    int warp = tid >> 5, lane = tid & 31;
    int g  = lane >> 2, tg = lane & 3;
    int wm = (warp >> 1) * 32;         // warp m-offset within tile
    int wn = (warp & 1)  * 32;         // warp n-offset within tile
    int bm = blockIdx.y * 128, bn = blockIdx.x * 64;

    float acc[2][4][4] = {};           // [mi][nj][frag]

    for (int k0 = 0; k0 < K; k0 += 32) {
        // --- load A tile (128x32) ---
        #pragma unroll
        for (int it = 0; it < 4; ++it) {
            int idx = tid + it * 256;          // 1024 float4 slots
            int r = idx >> 3, c4 = (idx & 7) << 2;
            float4 v = *(const float4*)(A + (size_t)(bm + r) * K + k0 + c4);
            v.x = cvt_tf32(v.x); v.y = cvt_tf32(v.y);
            v.z = cvt_tf32(v.z); v.w = cvt_tf32(v.w);
            *(float4*)(&As[r * GSTR + c4]) = v;
        }
        // --- load W tile (64x32) ---
        #pragma unroll
        for (int it = 0; it < 2; ++it) {
            int idx = tid + it * 256;          // 512 float4 slots
            int r = idx >> 3, c4 = (idx & 7) << 2;
            float4 v = *(const float4*)(W + (size_t)(bn + r) * K + k0 + c4);
            v.x = cvt_tf32(v.x); v.y = cvt_tf32(v.y);
            v.z = cvt_tf32(v.z); v.w = cvt_tf32(v.w);
            *(float4*)(&Bs[r * GSTR + c4]) = v;
        }
        __syncthreads();

        #pragma unroll
        for (int ks = 0; ks < 4; ++ks) {
            int kk = ks * 8;
            uint32_t a[2][4], b[4][2];
            #pragma unroll
            for (int mi = 0; mi < 2; ++mi) {
                int mrow = wm + mi * 16;
                a[mi][0] = __float_as_uint(As[(mrow + g    ) * GSTR + kk + tg    ]);
                a[mi][1] = __float_as_uint(As[(mrow + g + 8) * GSTR + kk + tg    ]);
                a[mi][2] = __float_as_uint(As[(mrow + g    ) * GSTR + kk + tg + 4]);
                a[mi][3] = __float_as_uint(As[(mrow + g + 8) * GSTR + kk + tg + 4]);
            }
            #pragma unroll
            for (int nj = 0; nj < 4; ++nj) {
                int nrow = wn + nj * 8;
                b[nj][0] = __float_as_uint(Bs[(nrow + g) * GSTR + kk + tg    ]);
                b[nj][1] = __float_as_uint(Bs[(nrow + g) * GSTR + kk + tg + 4]);
            }
            #pragma unroll
            for (int mi = 0; mi < 2; ++mi)
                #pragma unroll
                for (int nj = 0; nj < 4; ++nj)
                    mma_tf32(acc[mi][nj], a[mi], b[nj]);
        }
        __syncthreads();
    }

    // --- epilogue ---
    #pragma unroll
    for (int mi = 0; mi < 2; ++mi) {
        #pragma unroll
        for (int nj = 0; nj < 4; ++nj) {
            int r0 = bm + wm + mi * 16 + g;
            int c0 = bn + wn + nj * 8 + 2 * tg;
            float bv0 = bias[c0], bv1 = bias[c0 + 1];
            float v00 = acc[mi][nj][0] + bv0;
            float v01 = acc[mi][nj][1] + bv1;
            float v10 = acc[mi][nj][2] + bv0;
            float v11 = acc[mi][nj][3] + bv1;
            if (RELU) {
                v00 = fmaxf(v00, 0.f); v01 = fmaxf(v01, 0.f);
                v10 = fmaxf(v10, 0.f); v11 = fmaxf(v11, 0.f);
            }
            float2* p0 = (float2*)(C + (size_t)r0 * N + c0);
            float2* p1 = (float2*)(C + (size_t)(r0 + 8) * N + c0);
            if (RESID) {
                float2 o0 = *p0, o1 = *p1;
                v00 += o0.x; v01 += o0.y; v10 += o1.x; v11 += o1.y;
            }
            *p0 = make_float2(v00, v01);
            *p1 = make_float2(v10, v11);
        }
    }
}

// ---------------- attention: one CTA per (b,h), full K/V in smem ----------------
#define KV_STRIDE 33
#define ATTN_SMEM (2 * T_ * KV_STRIDE * 4)

__global__ void attn_kernel(const float* __restrict__ qkv,
                            float* __restrict__ attn_out)
{
    extern __shared__ float sm[];
    float* Ksh = sm;
    float* Vsh = sm + T_ * KV_STRIDE;

    int bh   = blockIdx.x;
    int b    = bh >> 3;
    int h    = bh & 7;
    int tid  = threadIdx.x;          // 512 threads = 16 warps
    int lane = tid & 31;
    int w    = tid >> 5;

    const float* kvbase = qkv + (size_t)b * T_ * (3*D_) + h * HD_;
    for (int idx = tid; idx < T_ * HD_; idx += 512) {
        int j = idx >> 5, d = idx & 31;
        Ksh[j*KV_STRIDE + d] = kvbase[(size_t)j * (3*D_) + D_   + d];
        Vsh[j*KV_STRIDE + d] = kvbase[(size_t)j * (3*D_) + 2*D_ + d];
    }
    __syncthreads();

    const float scale = 0.17677669529663687f;  // 1/sqrt(32)

    for (int qi = 0; qi < 32; ++qi) {
        int i = qi * 16 + w;
        float q[HD_];
        const float4* qp = (const float4*)(qkv + (size_t)(b*T_ + i) * (3*D_) + h * HD_);
        #pragma unroll
        for (int c = 0; c < 8; ++c) {
            float4 f = qp[c];
            q[4*c] = f.x; q[4*c+1] = f.y; q[4*c+2] = f.z; q[4*c+3] = f.w;
        }
        int jmax = ((i >> 3) + 1) << 3;
        int nsl  = (jmax + 31) >> 5;

        float s[16];
        float mx = -1e30f;
        #pragma unroll
        for (int slot = 0; slot < 16; ++slot) {
            float val = -1e30f;
            int j = slot * 32 + lane;
            if (slot < nsl && j < jmax) {
                const float* kr = Ksh + j * KV_STRIDE;
                float dot = 0.f;
                #pragma unroll
                for (int d = 0; d < HD_; ++d) dot = fmaf(q[d], kr[d], dot);
                val = dot * scale;
            }
            s[slot] = val;
            mx = fmaxf(mx, val);
        }
        #pragma unroll
        for (int off = 16; off; off >>= 1)
            mx = fmaxf(mx, __shfl_xor_sync(0xffffffffu, mx, off));

        float Z = 0.f;
        #pragma unroll
        for (int slot = 0; slot < 16; ++slot) {
            float p = __expf(s[slot] - mx);
            s[slot] = p;
            Z += p;
        }
        #pragma unroll
        for (int off = 16; off; off >>= 1)
            Z += __shfl_xor_sync(0xffffffffu, Z, off);
        float inv = 1.f / Z;

        float acc = 0.f;
        #pragma unroll
        for (int slot = 0; slot < 16; ++slot) {
            int jbase = slot * 32;
            if (jbase >= jmax) break;
            float ps = s[slot];
            int cnt = min(32, jmax - jbase);
            const float* vcol = Vsh + jbase * KV_STRIDE + lane;
            for (int src = 0; src < cnt; ++src) {
                float p = __shfl_sync(0xffffffffu, ps, src);
                acc = fmaf(p, vcol[src * KV_STRIDE], acc);
            }
        }
        attn_out[(size_t)(b*T_ + i) * D_ + h * HD_ + lane] = acc * inv;
    }
}

// ---------------- launch ----------------
extern "C" void kernel_launch(void* const* d_in, const int* in_sizes, int n_in,
                              void* d_out, int out_size)
{
    const float*         latents  = (const float*)d_in[0];
    const int*           move_ids = (const int*)d_in[1];
    const void*          mask     = d_in[2];
    const float*         pos      = (const float*)d_in[3];
    const float*         efrom    = (const float*)d_in[4];
    const float*         eto      = (const float*)d_in[5];
    const float*         epromo   = (const float*)d_in[6];
    const float*         in_proj_w= (const float*)d_in[7];
    const float*         in_proj_b= (const float*)d_in[8];
    const float*         out_w    = (const float*)d_in[9];
    const float*         out_b    = (const float*)d_in[10];
    const float*         fc1_w    = (const float*)d_in[11];
    const float*         fc1_b    = (const float*)d_in[12];
    const float*         fc2_w    = (const float*)d_in[13];
    const float*         fc2_b    = (const float*)d_in[14];
    const float*         norm_w   = (const float*)d_in[15];
    const float*         norm_b   = (const float*)d_in[16];
    float* out = (float*)d_out;

    float *px, *pln, *pqkv, *pattn, *ph1;
    cudaGetSymbolAddress((void**)&px,    g_x);
    cudaGetSymbolAddress((void**)&pln,   g_ln);
    cudaGetSymbolAddress((void**)&pqkv,  g_qkv);
    cudaGetSymbolAddress((void**)&pattn, g_attn);
    cudaGetSymbolAddress((void**)&ph1,   g_h1);

    cudaFuncSetAttribute(attn_kernel,
                         cudaFuncAttributeMaxDynamicSharedMemorySize, ATTN_SMEM);

    detect_mask_kernel<<<1, 256>>>((const unsigned char*)mask);
    embed_kernel<<<M_, 256>>>(latents, move_ids, pos, efrom, eto, epromo);

    for (int l = 0; l < L_; ++l) {
        ln_kernel<<<M_, 256>>>(px, norm_w, norm_b, pln);
        gemm_tf32_kernel<false,false><<<dim3(3*D_/64, M_/128), 256>>>(
            pln, in_proj_w + (size_t)l*3*D_*D_, in_proj_b + l*3*D_, pqkv, M_, 3*D_, D_);
        attn_kernel<<<B_*H_, 512, ATTN_SMEM>>>(pqkv, pattn);
        gemm_tf32_kernel<true,false><<<dim3(D_/64, M_/128), 256>>>(
            pattn, out_w + (size_t)l*D_*D_, out_b + l*D_, px, M_, D_, D_);
        ln_kernel<<<M_, 256>>>(px, norm_w, norm_b, pln);
        gemm_tf32_kernel<false,true><<<dim3(FF_/64, M_/128), 256>>>(
            pln, fc1_w + (size_t)l*FF_*D_, fc1_b + l*FF_, ph1, M_, FF_, D_);
        gemm_tf32_kernel<true,false><<<dim3(D_/64, M_/128), 256>>>(
            ph1, fc2_w + (size_t)l*D_*FF_, fc2_b + l*D_, px, M_, D_, FF_);
    }

    ln_mask_kernel<<<M_, 256>>>(px, norm_w, norm_b,
                                (const unsigned char*)mask, (const int*)mask,
                                latents, out);
}

// round 4
// speedup vs baseline: 1.5038x; 1.0002x over previous
#include <cuda_runtime.h>
#include <cuda_bf16.h>
#include <math.h>
#include <stdint.h>

// ---------------- problem constants ----------------
#define B_   64
#define T_   512
#define D_   256
#define FF_  512
#define L_   4
#define H_   8
#define HD_  32
#define M_   (B_*T_)          // 32768 rows

// ---------------- scratch (device globals; no allocation allowed) ----------------
__device__ float g_x   [M_*D_];     // running residual stream
__device__ float g_ln  [M_*D_];     // layernorm output
__device__ float g_qkv [M_*3*D_];   // qkv projections
__device__ float g_attn[M_*D_];     // attention output
__device__ float g_h1  [M_*FF_];    // ffn hidden
__device__ int   g_mask_u8;         // 1 if mask buffer is u8/bool, 0 if int32

// ---------------- mask dtype detection ----------------
__global__ void detect_mask_kernel(const unsigned char* __restrict__ m)
{
    __shared__ int s_any;
    if (threadIdx.x == 0) s_any = 0;
    __syncthreads();
    int any = 0;
    for (int i = threadIdx.x; i < M_; i += 256)
        if ((i & 3) && m[i]) any = 1;
    if (any) atomicOr(&s_any, 1);
    __syncthreads();
    if (threadIdx.x == 0) g_mask_u8 = s_any;
}

// ---------------- embedding ----------------
__global__ void embed_kernel(const float* __restrict__ latents,
                             const int*   __restrict__ move_ids,
                             const float* __restrict__ pos,
                             const float* __restrict__ efrom,
                             const float* __restrict__ eto,
                             const float* __restrict__ epromo)
{
    int row = blockIdx.x;
    int d   = threadIdx.x;
    int t   = row & (T_-1);
    int mid = move_ids[row];
    int promo = mid >> 12;
    int rem   = mid & 4095;
    int frm   = rem >> 6;
    int to    = rem & 63;
    size_t off = (size_t)row * D_ + d;
    g_x[off] = latents[off] + pos[t*D_ + d] + efrom[frm*D_ + d]
             + eto[to*D_ + d] + epromo[promo*D_ + d];
}

// ---------------- block reduce (256 threads) ----------------
__device__ __forceinline__ float blockReduceSum256(float v, float* red)
{
    __syncthreads();
    #pragma unroll
    for (int off = 16; off; off >>= 1) v += __shfl_xor_sync(0xffffffffu, v, off);
    int w = threadIdx.x >> 5;
    if ((threadIdx.x & 31) == 0) red[w] = v;
    __syncthreads();
    if (w == 0) {
        float s = (threadIdx.x < 8) ? red[threadIdx.x] : 0.f;
        s += __shfl_xor_sync(0xffffffffu, s, 4);
        s += __shfl_xor_sync(0xffffffffu, s, 2);
        s += __shfl_xor_sync(0xffffffffu, s, 1);
        if (threadIdx.x == 0) red[0] = s;
    }
    __syncthreads();
    return red[0];
}

// ---------------- layernorm: one CTA per row ----------------
__global__ void ln_kernel(const float* __restrict__ x,
                          const float* __restrict__ w,
                          const float* __restrict__ b,
                          float* __restrict__ y)
{
    __shared__ float red[8];
    size_t base = (size_t)blockIdx.x * D_;
    int t = threadIdx.x;
    float v = x[base + t];
    float mean = blockReduceSum256(v, red) * (1.f/(float)D_);
    float d = v - mean;
    float var = blockReduceSum256(d*d, red) * (1.f/(float)D_);
    y[base + t] = d * rsqrtf(var + 1e-5f) * w[t] + b[t];
}

// final layernorm + mask-select, writes d_out
__global__ void ln_mask_kernel(const float* __restrict__ x,
                               const float* __restrict__ w,
                               const float* __restrict__ b,
                               const unsigned char* __restrict__ mask_u8,
                               const int*           __restrict__ mask_i32,
                               const float* __restrict__ latents,
                               float* __restrict__ out)
{
    __shared__ float red[8];
    int row = blockIdx.x;
    size_t base = (size_t)row * D_;
    int t = threadIdx.x;
    float v = x[base + t];
    float mean = blockReduceSum256(v, red) * (1.f/(float)D_);
    float d = v - mean;
    float var = blockReduceSum256(d*d, red) * (1.f/(float)D_);
    float val = d * rsqrtf(var + 1e-5f) * w[t] + b[t];
    int m = g_mask_u8 ? (int)mask_u8[row] : mask_i32[row];
    out[base + t] = m ? val : latents[base + t];
}

// ---------------- tf32 tensor-core GEMM ----------------
// C[M,N] (+)= A[M,K] @ W[N,K]^T + bias[N]
// BM=128, BN=64, BK=32, 256 threads (8 warps, 4x2), warp tile 32x32,
// mma.sync m16n8k8 tf32. Smem row stride 36 floats -> LDS bank = 4g+tg,
// all 32 lanes distinct (conflict-free fragment loads).
__device__ __forceinline__ float cvt_tf32(float x)
{
    uint32_t u;
    asm("cvt.rna.tf32.f32 %0, %1;" : "=r"(u) : "f"(x));
    return __uint_as_float(u);
}

__device__ __forceinline__ void mma_tf32(float* d, const uint32_t* a, const uint32_t* b)
{
    asm volatile(
        "mma.sync.aligned.m16n8k8.row.col.f32.tf32.tf32.f32 "
        "{%0,%1,%2,%3},{%4,%5,%6,%7},{%8,%9},{%0,%1,%2,%3};"
        : "+f"(d[0]), "+f"(d[1]), "+f"(d[2]), "+f"(d[3])
        : "r"(a[0]), "r"(a[1]), "r"(a[2]), "r"(a[3]), "r"(b[0]), "r"(b[1]));
}

#define GSTR 36

template<bool RESID, bool RELU>
__global__ void gemm_tf32_kernel(const float* __restrict__ A,
                                 const float* __restrict__ W,
                                 const float* __restrict__ bias,
                                 float* __restrict__ C,
                                 int M, int N, int K)
{
    __shared__ float As[128 * GSTR];   // [m][k], 18KB
    __shared__ float Bs[ 64 * GSTR];   // [n][k],  9KB

    int tid  = threadIdx.x;
    int warp = tid >> 5, lane = tid & 31;
    int g  = lane >> 2, tg = lane & 3;
    int wm = (warp >> 1) * 32;         // warp m-offset within tile
    int wn = (warp & 1)  * 32;         // warp n-offset within tile
    int bm = blockIdx.y * 128, bn = blockIdx.x * 64;

    float acc[2][4][4] = {};           // [mi][nj][frag]

    for (int k0 = 0; k0 < K; k0 += 32) {
        // --- load A tile (128x32) ---
        #pragma unroll
        for (int it = 0; it < 4; ++it) {
            int idx = tid + it * 256;          // 1024 float4 slots
            int r = idx >> 3, c4 = (idx & 7) << 2;
            float4 v = *(const float4*)(A + (size_t)(bm + r) * K + k0 + c4);
            v.x = cvt_tf32(v.x); v.y = cvt_tf32(v.y);
            v.z = cvt_tf32(v.z); v.w = cvt_tf32(v.w);
            *(float4*)(&As[r * GSTR + c4]) = v;
        }
        // --- load W tile (64x32) ---
        #pragma unroll
        for (int it = 0; it < 2; ++it) {
            int idx = tid + it * 256;          // 512 float4 slots
            int r = idx >> 3, c4 = (idx & 7) << 2;
            float4 v = *(const float4*)(W + (size_t)(bn + r) * K + k0 + c4);
            v.x = cvt_tf32(v.x); v.y = cvt_tf32(v.y);
            v.z = cvt_tf32(v.z); v.w = cvt_tf32(v.w);
            *(float4*)(&Bs[r * GSTR + c4]) = v;
        }
        __syncthreads();

        #pragma unroll
        for (int ks = 0; ks < 4; ++ks) {
            int kk = ks * 8;
            uint32_t a[2][4], b[4][2];
            #pragma unroll
            for (int mi = 0; mi < 2; ++mi) {
                int mrow = wm + mi * 16;
                a[mi][0] = __float_as_uint(As[(mrow + g    ) * GSTR + kk + tg    ]);
                a[mi][1] = __float_as_uint(As[(mrow + g + 8) * GSTR + kk + tg    ]);
                a[mi][2] = __float_as_uint(As[(mrow + g    ) * GSTR + kk + tg + 4]);
                a[mi][3] = __float_as_uint(As[(mrow + g + 8) * GSTR + kk + tg + 4]);
            }
            #pragma unroll
            for (int nj = 0; nj < 4; ++nj) {
                int nrow = wn + nj * 8;
                b[nj][0] = __float_as_uint(Bs[(nrow + g) * GSTR + kk + tg    ]);
                b[nj][1] = __float_as_uint(Bs[(nrow + g) * GSTR + kk + tg + 4]);
            }
            #pragma unroll
            for (int mi = 0; mi < 2; ++mi)
                #pragma unroll
                for (int nj = 0; nj < 4; ++nj)
                    mma_tf32(acc[mi][nj], a[mi], b[nj]);
        }
        __syncthreads();
    }

    // --- epilogue ---
    #pragma unroll
    for (int mi = 0; mi < 2; ++mi) {
        #pragma unroll
        for (int nj = 0; nj < 4; ++nj) {
            int r0 = bm + wm + mi * 16 + g;
            int c0 = bn + wn + nj * 8 + 2 * tg;
            float bv0 = bias[c0], bv1 = bias[c0 + 1];
            float v00 = acc[mi][nj][0] + bv0;
            float v01 = acc[mi][nj][1] + bv1;
            float v10 = acc[mi][nj][2] + bv0;
            float v11 = acc[mi][nj][3] + bv1;
            if (RELU) {
                v00 = fmaxf(v00, 0.f); v01 = fmaxf(v01, 0.f);
                v10 = fmaxf(v10, 0.f); v11 = fmaxf(v11, 0.f);
            }
            float2* p0 = (float2*)(C + (size_t)r0 * N + c0);
            float2* p1 = (float2*)(C + (size_t)(r0 + 8) * N + c0);
            if (RESID) {
                float2 o0 = *p0, o1 = *p1;
                v00 += o0.x; v01 += o0.y; v10 += o1.x; v11 += o1.y;
            }
            *p0 = make_float2(v00, v01);
            *p1 = make_float2(v10, v11);
        }
    }
}

// ---------------- attention: one CTA per (b,h), full K/V in smem ----------------
#define KV_STRIDE 33
#define ATTN_SMEM (2 * T_ * KV_STRIDE * 4)

__global__ void attn_kernel(const float* __restrict__ qkv,
                            float* __restrict__ attn_out)
{
    extern __shared__ float sm[];
    float* Ksh = sm;
    float* Vsh = sm + T_ * KV_STRIDE;

    int bh   = blockIdx.x;
    int b    = bh >> 3;
    int h    = bh & 7;
    int tid  = threadIdx.x;          // 512 threads = 16 warps
    int lane = tid & 31;
    int w    = tid >> 5;

    const float* kvbase = qkv + (size_t)b * T_ * (3*D_) + h * HD_;
    for (int idx = tid; idx < T_ * HD_; idx += 512) {
        int j = idx >> 5, d = idx & 31;
        Ksh[j*KV_STRIDE + d] = kvbase[(size_t)j * (3*D_) + D_   + d];
        Vsh[j*KV_STRIDE + d] = kvbase[(size_t)j * (3*D_) + 2*D_ + d];
    }
    __syncthreads();

    const float scale = 0.17677669529663687f;  // 1/sqrt(32)

    for (int qi = 0; qi < 32; ++qi) {
        int i = qi * 16 + w;
        float q[HD_];
        const float4* qp = (const float4*)(qkv + (size_t)(b*T_ + i) * (3*D_) + h * HD_);
        #pragma unroll
        for (int c = 0; c < 8; ++c) {
            float4 f = qp[c];
            q[4*c] = f.x; q[4*c+1] = f.y; q[4*c+2] = f.z; q[4*c+3] = f.w;
        }
        int jmax = ((i >> 3) + 1) << 3;
        int nsl  = (jmax + 31) >> 5;

        float s[16];
        float mx = -1e30f;
        #pragma unroll
        for (int slot = 0; slot < 16; ++slot) {
            float val = -1e30f;
            int j = slot * 32 + lane;
            if (slot < nsl && j < jmax) {
                const float* kr = Ksh + j * KV_STRIDE;
                float dot = 0.f;
                #pragma unroll
                for (int d = 0; d < HD_; ++d) dot = fmaf(q[d], kr[d], dot);
                val = dot * scale;
            }
            s[slot] = val;
            mx = fmaxf(mx, val);
        }
        #pragma unroll
        for (int off = 16; off; off >>= 1)
            mx = fmaxf(mx, __shfl_xor_sync(0xffffffffu, mx, off));

        float Z = 0.f;
        #pragma unroll
        for (int slot = 0; slot < 16; ++slot) {
            float p = __expf(s[slot] - mx);
            s[slot] = p;
            Z += p;
        }
        #pragma unroll
        for (int off = 16; off; off >>= 1)
            Z += __shfl_xor_sync(0xffffffffu, Z, off);
        float inv = 1.f / Z;

        float acc = 0.f;
        #pragma unroll
        for (int slot = 0; slot < 16; ++slot) {
            int jbase = slot * 32;
            if (jbase >= jmax) break;
            float ps = s[slot];
            int cnt = min(32, jmax - jbase);
            const float* vcol = Vsh + jbase * KV_STRIDE + lane;
            for (int src = 0; src < cnt; ++src) {
                float p = __shfl_sync(0xffffffffu, ps, src);
                acc = fmaf(p, vcol[src * KV_STRIDE], acc);
            }
        }
        attn_out[(size_t)(b*T_ + i) * D_ + h * HD_ + lane] = acc * inv;
    }
}

// ---------------- launch ----------------
extern "C" void kernel_launch(void* const* d_in, const int* in_sizes, int n_in,
                              void* d_out, int out_size)
{
    const float*         latents  = (const float*)d_in[0];
    const int*           move_ids = (const int*)d_in[1];
    const void*          mask     = d_in[2];
    const float*         pos      = (const float*)d_in[3];
    const float*         efrom    = (const float*)d_in[4];
    const float*         eto      = (const float*)d_in[5];
    const float*         epromo   = (const float*)d_in[6];
    const float*         in_proj_w= (const float*)d_in[7];
    const float*         in_proj_b= (const float*)d_in[8];
    const float*         out_w    = (const float*)d_in[9];
    const float*         out_b    = (const float*)d_in[10];
    const float*         fc1_w    = (const float*)d_in[11];
    const float*         fc1_b    = (const float*)d_in[12];
    const float*         fc2_w    = (const float*)d_in[13];
    const float*         fc2_b    = (const float*)d_in[14];
    const float*         norm_w   = (const float*)d_in[15];
    const float*         norm_b   = (const float*)d_in[16];
    float* out = (float*)d_out;

    float *px, *pln, *pqkv, *pattn, *ph1;
    cudaGetSymbolAddress((void**)&px,    g_x);
    cudaGetSymbolAddress((void**)&pln,   g_ln);
    cudaGetSymbolAddress((void**)&pqkv,  g_qkv);
    cudaGetSymbolAddress((void**)&pattn, g_attn);
    cudaGetSymbolAddress((void**)&ph1,   g_h1);

    cudaFuncSetAttribute(attn_kernel,
                         cudaFuncAttributeMaxDynamicSharedMemorySize, ATTN_SMEM);

    detect_mask_kernel<<<1, 256>>>((const unsigned char*)mask);
    embed_kernel<<<M_, 256>>>(latents, move_ids, pos, efrom, eto, epromo);

    for (int l = 0; l < L_; ++l) {
        ln_kernel<<<M_, 256>>>(px, norm_w, norm_b, pln);
        gemm_tf32_kernel<false,false><<<dim3(3*D_/64, M_/128), 256>>>(
            pln, in_proj_w + (size_t)l*3*D_*D_, in_proj_b + l*3*D_, pqkv, M_, 3*D_, D_);
        attn_kernel<<<B_*H_, 512, ATTN_SMEM>>>(pqkv, pattn);
        gemm_tf32_kernel<true,false><<<dim3(D_/64, M_/128), 256>>>(
            pattn, out_w + (size_t)l*D_*D_, out_b + l*D_, px, M_, D_, D_);
        ln_kernel<<<M_, 256>>>(px, norm_w, norm_b, pln);
        gemm_tf32_kernel<false,true><<<dim3(FF_/64, M_/128), 256>>>(
            pln, fc1_w + (size_t)l*FF_*D_, fc1_b + l*FF_, ph1, M_, FF_, D_);
        gemm_tf32_kernel<true,false><<<dim3(D_/64, M_/128), 256>>>(
            ph1, fc2_w + (size_t)l*D_*FF_, fc2_b + l*D_, px, M_, D_, FF_);
    }

    ln_mask_kernel<<<M_, 256>>>(px, norm_w, norm_b,
                                (const unsigned char*)mask, (const int*)mask,
                                latents, out);
}